// round 4
// baseline (speedup 1.0000x reference)
#include <cuda_runtime.h>
#include <cuda_bf16.h>
#include <cstdint>

// ---------------------------------------------------------------------------
// DynamicLoRALinear on GB300 (sm_103 baseline PTX; tcgen05 not available)
//   out = x @ W^T + b + SCALING * ((x @ A[slot]) @ B[slot])
//
//   1) 3xBF16 split, K folded: logical K' = 12288, term order
//      [xh*wh | xl*wh | xh*wl], stored dedup as x'=[xh|xl], w'=[wh|wl].
//   2) mma.sync.m16n8k16 GEMM: CTA 128x128, 8 warps (64x32 warp tile),
//      3-stage cp.async pipeline interleaved into the MMA stream,
//      SW128 swizzle + XOR-folded ldmatrix addressing, <=128 regs so
//      2 CTAs/SM (16 warps/SM). Fused epilogue: bias + 2*h@B[slot].
//   3) fp32 SIMT kernel for lora_h = x@A.
// ---------------------------------------------------------------------------

#define DINLINE __device__ __forceinline__

static constexpr int BB    = 8;
static constexpr int TT    = 1024;
static constexpr int INF   = 4096;
static constexpr int OUTF  = 4096;
static constexpr int RR    = 16;
static constexpr int M_TOT = BB * TT;          // 8192
static constexpr int KW    = 2 * INF;          // physical row width 8192
static constexpr int NCH   = 192;              // logical K' chunks of 64
static constexpr float SCALING_F = 2.0f;       // ALPHA/R

// ------------------------- scratch (device globals) ------------------------
__device__ __align__(128) __nv_bfloat16 g_xa[(size_t)M_TOT * KW]; // [xh|xl]
__device__ __align__(128) __nv_bfloat16 g_wb[(size_t)OUTF  * KW]; // [wh|wl]
__device__ __align__(128) float         g_h[M_TOT * RR];

// ------------------------------ PTX helpers --------------------------------
DINLINE uint32_t smem_u32(const void* p) {
    uint32_t a;
    asm("{ .reg .u64 t; cvta.to.shared.u64 t, %1; cvt.u32.u64 %0, t; }"
        : "=r"(a) : "l"(p));
    return a;
}

#define SW128(off) ((off) ^ (((off) >> 3) & 0x70))

#define CP_ASYNC16(dst, src) \
    asm volatile("cp.async.cg.shared.global [%0], [%1], 16;" :: "r"(dst), "l"(src) : "memory")
#define CP_COMMIT() asm volatile("cp.async.commit_group;" ::: "memory")
#define CP_WAIT_1() asm volatile("cp.async.wait_group 1;" ::: "memory")
#define CP_WAIT_0() asm volatile("cp.async.wait_group 0;" ::: "memory")

#define LDSM_X4(r0, r1, r2, r3, a) \
    asm volatile("ldmatrix.sync.aligned.m8n8.x4.shared.b16 {%0,%1,%2,%3}, [%4];" \
                 : "=r"(r0), "=r"(r1), "=r"(r2), "=r"(r3) : "r"(a))

DINLINE void mma_bf16(float* d, const uint32_t* a, uint32_t b0, uint32_t b1) {
    asm volatile(
        "mma.sync.aligned.m16n8k16.row.col.f32.bf16.bf16.f32 "
        "{%0,%1,%2,%3}, {%4,%5,%6,%7}, {%8,%9}, {%0,%1,%2,%3};"
        : "+f"(d[0]), "+f"(d[1]), "+f"(d[2]), "+f"(d[3])
        : "r"(a[0]), "r"(a[1]), "r"(a[2]), "r"(a[3]), "r"(b0), "r"(b1));
}

// ---------------------------------------------------------------------------
// K1: split fp32 rows of INF -> bf16 rows of KW: hi at [k], lo at [INF+k]
// ---------------------------------------------------------------------------
__global__ void __launch_bounds__(256)
k_split(const float* __restrict__ in, __nv_bfloat16* __restrict__ out, int total4) {
    const int stride = gridDim.x * blockDim.x;
    for (int i = blockIdx.x * blockDim.x + threadIdx.x; i < total4; i += stride) {
        const int row = i >> 10, c4 = i & 1023;
        float4 v = ((const float4*)in)[i];
        __nv_bfloat16 h0 = __float2bfloat16(v.x);
        __nv_bfloat16 h1 = __float2bfloat16(v.y);
        __nv_bfloat16 h2 = __float2bfloat16(v.z);
        __nv_bfloat16 h3 = __float2bfloat16(v.w);
        __nv_bfloat162 hA = {h0, h1}, hB = {h2, h3};
        __nv_bfloat162 lA = {__float2bfloat16(v.x - __bfloat162float(h0)),
                             __float2bfloat16(v.y - __bfloat162float(h1))};
        __nv_bfloat162 lB = {__float2bfloat16(v.z - __bfloat162float(h2)),
                             __float2bfloat16(v.w - __bfloat162float(h3))};
        const size_t rb = (size_t)row * KW;
        __nv_bfloat162* p;
        p = (__nv_bfloat162*)(out + rb + c4 * 4);        p[0] = hA; p[1] = hB;
        p = (__nv_bfloat162*)(out + rb + INF + c4 * 4);  p[0] = lA; p[1] = lB;
    }
}

// ---------------------------------------------------------------------------
// K2: lora_h[m][r] = sum_k x[m][k] * A[slot(m)][k][r]    (fp32)
// ---------------------------------------------------------------------------
__global__ void __launch_bounds__(256)
k_lorah(const float* __restrict__ x, const float* __restrict__ As,
        const int* __restrict__ map, float* __restrict__ h) {
    __shared__ float sA[256 * 16];
    __shared__ float sP[64 * 4 * 16];
    const int tid = threadIdx.x;
    const int m0  = blockIdx.x * 64;
    const int slot = map[m0 / TT];
    const float* Abase = As + (size_t)slot * INF * RR;
    const int tt = tid >> 2;
    const int q  = tid & 3;
    const float* xrow = x + (size_t)(m0 + tt) * INF;

    float acc[16];
#pragma unroll
    for (int r = 0; r < 16; ++r) acc[r] = 0.f;

    for (int c = 0; c < 16; ++c) {
        __syncthreads();
        const float4* src = (const float4*)(Abase + (size_t)c * 256 * 16);
#pragma unroll
        for (int ii = 0; ii < 4; ++ii)
            ((float4*)sA)[tid + ii * 256] = src[tid + ii * 256];
        __syncthreads();
#pragma unroll 4
        for (int jj = 0; jj < 16; ++jj) {
            int kloc = 16 * jj + 4 * q;
            float4 xv = *(const float4*)(xrow + c * 256 + kloc);
#pragma unroll
            for (int e = 0; e < 4; ++e) {
                float xs = (e == 0) ? xv.x : (e == 1) ? xv.y : (e == 2) ? xv.z : xv.w;
                const float* Ar = sA + (kloc + e) * 16;
#pragma unroll
                for (int r = 0; r < 16; ++r) acc[r] += xs * Ar[r];
            }
        }
    }
    __syncthreads();
#pragma unroll
    for (int r = 0; r < 16; ++r) sP[(tt * 4 + q) * 16 + r] = acc[r];
    __syncthreads();
    for (int o = tid; o < 64 * 16; o += 256) {
        int token = o >> 4, r = o & 15;
        float s = sP[(token * 4 + 0) * 16 + r] + sP[(token * 4 + 1) * 16 + r]
                + sP[(token * 4 + 2) * 16 + r] + sP[(token * 4 + 3) * 16 + r];
        h[(m0 + token) * 16 + r] = s;
    }
}

// ---------------------------------------------------------------------------
// K3: GEMM + fused epilogue. CTA 128x128, 256 threads, warp grid 2x4.
// ---------------------------------------------------------------------------
static constexpr int TILE_B  = 128 * 128;      // 16KB
static constexpr int STAGE_B = 2 * TILE_B;     // 32KB
static constexpr int STAGES  = 3;
static constexpr uint32_t GEMM_SMEM = STAGES * STAGE_B + 1024;
static constexpr int ROWSTRIDE_B = KW * 2;     // 16384 bytes per gmem row

DINLINE int kmapA(int c) { return c < 128 ? c : c - 128; }  // [xh|xl|xh]
DINLINE int kmapB(int c) { return c < 64  ? c : c - 64;  }  // [wh|wh|wl]

__global__ void __launch_bounds__(256, 2)
k_gemm(const __nv_bfloat16* __restrict__ Abuf,
       const __nv_bfloat16* __restrict__ Bbuf,
       const float* __restrict__ bias,
       const float* __restrict__ Bs,
       const int* __restrict__ map,
       const float* __restrict__ h,
       float* __restrict__ out) {
    extern __shared__ char smraw[];
    const uint32_t raw  = smem_u32(smraw);
    const uint32_t base = (raw + 1023u) & ~1023u;
    char* p_base = smraw + (base - raw);
    const int tid = threadIdx.x, wid = tid >> 5, lane = tid & 31;
    const int wm = wid >> 2, wn = wid & 3;     // 2x4 warp grid, tile 64x32
    const int m0 = blockIdx.y * 128, n0 = blockIdx.x * 128;

    // per-thread cp.async geometry: 4 A units + 4 B units per stage
    const char* gAt = (const char*)(Abuf + (size_t)m0 * KW)
                      + (size_t)(tid >> 3) * ROWSTRIDE_B + (tid & 7) * 16;
    const char* gBt = (const char*)(Bbuf + (size_t)n0 * KW)
                      + (size_t)(tid >> 3) * ROWSTRIDE_B + (tid & 7) * 16;
    uint32_t offs[4];
#pragma unroll
    for (int j = 0; j < 4; ++j)
        offs[j] = SW128((uint32_t)((((tid >> 3) + 32 * j) * 128) + (tid & 7) * 16));

    auto load_full = [&](int s, int c) {
        const uint32_t sb = base + s * STAGE_B;
        const int kbA = kmapA(c) * 128, kbB = kmapB(c) * 128;
#pragma unroll
        for (int j = 0; j < 4; ++j) {
            CP_ASYNC16(sb + offs[j], gAt + (size_t)j * (32 * ROWSTRIDE_B) + kbA);
            CP_ASYNC16(sb + TILE_B + offs[j], gBt + (size_t)j * (32 * ROWSTRIDE_B) + kbB);
        }
        CP_COMMIT();
    };

    load_full(0, 0);
    load_full(1, 1);

    float acc[4][4][4];
#pragma unroll
    for (int a = 0; a < 4; ++a)
#pragma unroll
        for (int b = 0; b < 4; ++b)
#pragma unroll
            for (int c = 0; c < 4; ++c) acc[a][b][c] = 0.f;

    // XOR-folded ldmatrix addressing: pre[t] holds row bytes | (lkh ^ mask);
    // per-ks address = (stage_base + pre[t]) ^ (ks*32).
    const int lrow = lane & 15;
    const uint32_t lkh = (uint32_t)((lane >> 4) << 4);
    uint32_t preA[4], preB[2];
#pragma unroll
    for (int t = 0; t < 4; ++t) {
        uint32_t rb = (uint32_t)((wm * 64 + t * 16 + lrow) * 128);
        preA[t] = rb | (lkh ^ ((rb >> 3) & 0x70));
    }
#pragma unroll
    for (int t = 0; t < 2; ++t) {
        uint32_t rb = (uint32_t)((wn * 32 + t * 16 + lrow) * 128);
        preB[t] = rb | (lkh ^ ((rb >> 3) & 0x70));
    }

    for (int i = 0; i < NCH; ++i) {
        if (i == NCH - 1) { CP_WAIT_0(); } else { CP_WAIT_1(); }
        __syncthreads();
        const bool doload = (i + 2 < NCH);
        const uint32_t sld = base + ((i + 2) % STAGES) * STAGE_B;
        const int kbA = kmapA(i + 2) * 128, kbB = kmapB(i + 2) * 128;
        const uint32_t sA = base + (i % STAGES) * STAGE_B;
        const uint32_t sB = sA + TILE_B;
        uint32_t bA[4], bB[2];
#pragma unroll
        for (int t = 0; t < 4; ++t) bA[t] = sA + preA[t];
#pragma unroll
        for (int t = 0; t < 2; ++t) bB[t] = sB + preB[t];
#pragma unroll
        for (int ks = 0; ks < 4; ++ks) {
            if (doload) {   // 2 of the 8 next-stage cp.async per ks
                CP_ASYNC16(sld + offs[ks],
                           gAt + (size_t)ks * (32 * ROWSTRIDE_B) + kbA);
                CP_ASYNC16(sld + TILE_B + offs[ks],
                           gBt + (size_t)ks * (32 * ROWSTRIDE_B) + kbB);
            }
            const uint32_t kx = (uint32_t)(ks << 5);
            uint32_t ar[4][4], br[2][4];
#pragma unroll
            for (int t = 0; t < 4; ++t)
                LDSM_X4(ar[t][0], ar[t][1], ar[t][2], ar[t][3], bA[t] ^ kx);
#pragma unroll
            for (int t = 0; t < 2; ++t)
                LDSM_X4(br[t][0], br[t][1], br[t][2], br[t][3], bB[t] ^ kx);
#pragma unroll
            for (int tm = 0; tm < 4; ++tm)
#pragma unroll
                for (int tn = 0; tn < 4; ++tn)
                    mma_bf16(acc[tm][tn], ar[tm],
                             br[tn >> 1][tn & 1], br[tn >> 1][2 + (tn & 1)]);
        }
        if (doload) CP_COMMIT();
    }

    // ------------- fused epilogue: out = acc + bias + 2 * h @ B[slot] -------
    __syncthreads();                       // stage smem now reusable
    float* sH    = (float*)p_base;         // 128 x 16 (8KB)
    float* sBm   = sH + 2048;              // 16 x 128 (8KB)
    float* sbias = sBm + 2048;             // 128 (512B)
    const int slot = map[m0 >> 10];
    {
        const float4* hs = (const float4*)(h + (size_t)m0 * 16);
#pragma unroll
        for (int q = tid; q < 512; q += 256) ((float4*)sH)[q] = hs[q];
        const float* Bbase = Bs + (size_t)slot * RR * OUTF + n0;
#pragma unroll
        for (int q = tid; q < 512; q += 256) {
            int r = q >> 5, c4 = q & 31;
            ((float4*)sBm)[q] = *(const float4*)(Bbase + (size_t)r * OUTF + c4 * 4);
        }
        if (tid < 32) ((float4*)sbias)[tid] = ((const float4*)(bias + n0))[tid];
    }
    __syncthreads();

    const int erow = lane >> 2, ecol = (lane & 3) * 2;
#pragma unroll
    for (int tm = 0; tm < 4; ++tm) {
        const int r0 = wm * 64 + tm * 16 + erow;
        float h0[16], h1[16];
#pragma unroll
        for (int r = 0; r < 16; ++r) { h0[r] = sH[r0 * 16 + r]; h1[r] = sH[(r0 + 8) * 16 + r]; }
#pragma unroll
        for (int tn = 0; tn < 4; ++tn) {
            const int nl = wn * 32 + tn * 8 + ecol;
            float d00 = 0.f, d01 = 0.f, d10 = 0.f, d11 = 0.f;
#pragma unroll
            for (int r = 0; r < 16; ++r) {
                float B0 = sBm[r * 128 + nl], B1 = sBm[r * 128 + nl + 1];
                d00 += h0[r] * B0; d01 += h0[r] * B1;
                d10 += h1[r] * B0; d11 += h1[r] * B1;
            }
            const float b0 = sbias[nl], b1 = sbias[nl + 1];
            float* p = out + (size_t)(m0 + r0) * OUTF + n0 + nl;
            *(float2*)p = make_float2(acc[tm][tn][0] + b0 + SCALING_F * d00,
                                      acc[tm][tn][1] + b1 + SCALING_F * d01);
            *(float2*)(p + (size_t)8 * OUTF) =
                make_float2(acc[tm][tn][2] + b0 + SCALING_F * d10,
                            acc[tm][tn][3] + b1 + SCALING_F * d11);
        }
    }
}

// ---------------------------------------------------------------------------
extern "C" void kernel_launch(void* const* d_in, const int* in_sizes, int n_in,
                              void* d_out, int out_size) {
    const float* x    = (const float*)d_in[0];
    const int*   map  = (const int*)d_in[1];
    const float* W    = (const float*)d_in[2];
    const float* bias = (const float*)d_in[3];
    const float* As   = (const float*)d_in[4];
    const float* Bs   = (const float*)d_in[5];
    float* out = (float*)d_out;

    __nv_bfloat16 *xa, *wb;
    float* hbuf;
    cudaGetSymbolAddress((void**)&xa, g_xa);
    cudaGetSymbolAddress((void**)&wb, g_wb);
    cudaGetSymbolAddress((void**)&hbuf, g_h);

    cudaFuncSetAttribute(k_gemm, cudaFuncAttributeMaxDynamicSharedMemorySize,
                         (int)GEMM_SMEM);

    k_split<<<2048, 256>>>(x, xa, M_TOT * (INF / 4));
    k_split<<<1024, 256>>>(W, wb, OUTF * (INF / 4));
    k_lorah<<<M_TOT / 64, 256>>>(x, As, map, hbuf);
    k_gemm<<<dim3(OUTF / 128, M_TOT / 128), 256, GEMM_SMEM>>>(
        xa, wb, bias, Bs, map, hbuf, out);
}

// round 5
// speedup vs baseline: 1.0347x; 1.0347x over previous
#include <cuda_runtime.h>
#include <cuda_bf16.h>
#include <cstdint>

// ---------------------------------------------------------------------------
// DynamicLoRALinear on GB300 (sm_103 baseline PTX; tcgen05 not available)
//   out = x @ W^T + b + SCALING * ((x @ A[slot]) @ B[slot])
//
//   1) 3xBF16 split, K folded: logical K' = 12288, term order
//      [xh*wh | xl*wh | xh*wl], stored dedup as x'=[xh|xl], w'=[wh|wl].
//   2) mma.sync.m16n8k16 GEMM: CTA 128x128, 4 warps (64x64 warp tile =
//      minimal LDSM/FLOP), 3-stage cp.async pipeline, SW128 swizzle,
//      XOR-folded addressing, register double-buffered fragments.
//      Fused epilogue: bias + 2*h@B[slot].
//   3) fp32 SIMT kernel for lora_h = x@A.
// ---------------------------------------------------------------------------

#define DINLINE __device__ __forceinline__

static constexpr int BB    = 8;
static constexpr int TT    = 1024;
static constexpr int INF   = 4096;
static constexpr int OUTF  = 4096;
static constexpr int RR    = 16;
static constexpr int M_TOT = BB * TT;          // 8192
static constexpr int KW    = 2 * INF;          // physical row width 8192
static constexpr int NCH   = 192;              // logical K' chunks of 64
static constexpr float SCALING_F = 2.0f;       // ALPHA/R

// ------------------------- scratch (device globals) ------------------------
__device__ __align__(128) __nv_bfloat16 g_xa[(size_t)M_TOT * KW]; // [xh|xl]
__device__ __align__(128) __nv_bfloat16 g_wb[(size_t)OUTF  * KW]; // [wh|wl]
__device__ __align__(128) float         g_h[M_TOT * RR];

// ------------------------------ PTX helpers --------------------------------
DINLINE uint32_t smem_u32(const void* p) {
    uint32_t a;
    asm("{ .reg .u64 t; cvta.to.shared.u64 t, %1; cvt.u32.u64 %0, t; }"
        : "=r"(a) : "l"(p));
    return a;
}

#define SW128(off) ((off) ^ (((off) >> 3) & 0x70))

#define CP_ASYNC16(dst, src) \
    asm volatile("cp.async.cg.shared.global [%0], [%1], 16;" :: "r"(dst), "l"(src) : "memory")
#define CP_COMMIT() asm volatile("cp.async.commit_group;" ::: "memory")
#define CP_WAIT_1() asm volatile("cp.async.wait_group 1;" ::: "memory")
#define CP_WAIT_0() asm volatile("cp.async.wait_group 0;" ::: "memory")

#define LDSM_X4(r0, r1, r2, r3, a) \
    asm volatile("ldmatrix.sync.aligned.m8n8.x4.shared.b16 {%0,%1,%2,%3}, [%4];" \
                 : "=r"(r0), "=r"(r1), "=r"(r2), "=r"(r3) : "r"(a))

DINLINE void mma_bf16(float* d, const uint32_t* a, uint32_t b0, uint32_t b1) {
    asm volatile(
        "mma.sync.aligned.m16n8k16.row.col.f32.bf16.bf16.f32 "
        "{%0,%1,%2,%3}, {%4,%5,%6,%7}, {%8,%9}, {%0,%1,%2,%3};"
        : "+f"(d[0]), "+f"(d[1]), "+f"(d[2]), "+f"(d[3])
        : "r"(a[0]), "r"(a[1]), "r"(a[2]), "r"(a[3]), "r"(b0), "r"(b1));
}

// ---------------------------------------------------------------------------
// K1: split fp32 rows of INF -> bf16 rows of KW: hi at [k], lo at [INF+k]
// ---------------------------------------------------------------------------
__global__ void __launch_bounds__(256)
k_split(const float* __restrict__ in, __nv_bfloat16* __restrict__ out, int total4) {
    const int stride = gridDim.x * blockDim.x;
    for (int i = blockIdx.x * blockDim.x + threadIdx.x; i < total4; i += stride) {
        const int row = i >> 10, c4 = i & 1023;
        float4 v = ((const float4*)in)[i];
        __nv_bfloat16 h0 = __float2bfloat16(v.x);
        __nv_bfloat16 h1 = __float2bfloat16(v.y);
        __nv_bfloat16 h2 = __float2bfloat16(v.z);
        __nv_bfloat16 h3 = __float2bfloat16(v.w);
        __nv_bfloat162 hA = {h0, h1}, hB = {h2, h3};
        __nv_bfloat162 lA = {__float2bfloat16(v.x - __bfloat162float(h0)),
                             __float2bfloat16(v.y - __bfloat162float(h1))};
        __nv_bfloat162 lB = {__float2bfloat16(v.z - __bfloat162float(h2)),
                             __float2bfloat16(v.w - __bfloat162float(h3))};
        const size_t rb = (size_t)row * KW;
        __nv_bfloat162* p;
        p = (__nv_bfloat162*)(out + rb + c4 * 4);        p[0] = hA; p[1] = hB;
        p = (__nv_bfloat162*)(out + rb + INF + c4 * 4);  p[0] = lA; p[1] = lB;
    }
}

// ---------------------------------------------------------------------------
// K2: lora_h[m][r] = sum_k x[m][k] * A[slot(m)][k][r]    (fp32)
// ---------------------------------------------------------------------------
__global__ void __launch_bounds__(256)
k_lorah(const float* __restrict__ x, const float* __restrict__ As,
        const int* __restrict__ map, float* __restrict__ h) {
    __shared__ float sA[256 * 16];
    __shared__ float sP[64 * 4 * 16];
    const int tid = threadIdx.x;
    const int m0  = blockIdx.x * 64;
    const int slot = map[m0 / TT];
    const float* Abase = As + (size_t)slot * INF * RR;
    const int tt = tid >> 2;
    const int q  = tid & 3;
    const float* xrow = x + (size_t)(m0 + tt) * INF;

    float acc[16];
#pragma unroll
    for (int r = 0; r < 16; ++r) acc[r] = 0.f;

    for (int c = 0; c < 16; ++c) {
        __syncthreads();
        const float4* src = (const float4*)(Abase + (size_t)c * 256 * 16);
#pragma unroll
        for (int ii = 0; ii < 4; ++ii)
            ((float4*)sA)[tid + ii * 256] = src[tid + ii * 256];
        __syncthreads();
#pragma unroll 4
        for (int jj = 0; jj < 16; ++jj) {
            int kloc = 16 * jj + 4 * q;
            float4 xv = *(const float4*)(xrow + c * 256 + kloc);
#pragma unroll
            for (int e = 0; e < 4; ++e) {
                float xs = (e == 0) ? xv.x : (e == 1) ? xv.y : (e == 2) ? xv.z : xv.w;
                const float* Ar = sA + (kloc + e) * 16;
#pragma unroll
                for (int r = 0; r < 16; ++r) acc[r] += xs * Ar[r];
            }
        }
    }
    __syncthreads();
#pragma unroll
    for (int r = 0; r < 16; ++r) sP[(tt * 4 + q) * 16 + r] = acc[r];
    __syncthreads();
    for (int o = tid; o < 64 * 16; o += 256) {
        int token = o >> 4, r = o & 15;
        float s = sP[(token * 4 + 0) * 16 + r] + sP[(token * 4 + 1) * 16 + r]
                + sP[(token * 4 + 2) * 16 + r] + sP[(token * 4 + 3) * 16 + r];
        h[(m0 + token) * 16 + r] = s;
    }
}

// ---------------------------------------------------------------------------
// K3: GEMM + fused epilogue. CTA 128x128, 128 threads, warp grid 2x2 (64x64).
// ---------------------------------------------------------------------------
static constexpr int TILE_B  = 128 * 128;      // 16KB
static constexpr int STAGE_B = 2 * TILE_B;     // 32KB
static constexpr int STAGES  = 3;
static constexpr uint32_t GEMM_SMEM = STAGES * STAGE_B + 1024;
static constexpr int ROWSTRIDE_B = KW * 2;     // 16384 bytes per gmem row

__global__ void __launch_bounds__(128, 2)
k_gemm(const __nv_bfloat16* __restrict__ Abuf,
       const __nv_bfloat16* __restrict__ Bbuf,
       const float* __restrict__ bias,
       const float* __restrict__ Bs,
       const int* __restrict__ map,
       const float* __restrict__ h,
       float* __restrict__ out) {
    extern __shared__ char smraw[];
    const uint32_t raw  = smem_u32(smraw);
    const uint32_t base = (raw + 1023u) & ~1023u;
    char* p_base = smraw + (base - raw);
    const int tid = threadIdx.x, wid = tid >> 5, lane = tid & 31;
    const int wm = wid >> 1, wn = wid & 1;     // 2x2 warp grid, tile 64x64
    const int m0 = blockIdx.y * 128, n0 = blockIdx.x * 128;

    // per-thread cp.async geometry: 8 A units + 8 B units per stage
    // (16 rows apart). Prefetch pointers advance by 128B per chunk; reset at
    // the hi->lo / hi->hi segment wraps (chunk 128 for A, chunk 64 for B).
    const char* gAt = (const char*)(Abuf + (size_t)m0 * KW)
                      + (size_t)(tid >> 3) * ROWSTRIDE_B + (tid & 7) * 16;
    const char* gBt = (const char*)(Bbuf + (size_t)n0 * KW)
                      + (size_t)(tid >> 3) * ROWSTRIDE_B + (tid & 7) * 16;
    uint32_t offs[8];
#pragma unroll
    for (int ii = 0; ii < 8; ++ii)
        offs[ii] = SW128((uint32_t)((((tid >> 3) + 16 * ii) * 128) + (tid & 7) * 16));

    auto load_full = [&](int s, int kbA, int kbB) {
        const uint32_t sb = base + s * STAGE_B;
#pragma unroll
        for (int ii = 0; ii < 8; ++ii)
            CP_ASYNC16(sb + offs[ii], gAt + (size_t)ii * (16 * ROWSTRIDE_B) + kbA);
#pragma unroll
        for (int ii = 0; ii < 8; ++ii)
            CP_ASYNC16(sb + TILE_B + offs[ii], gBt + (size_t)ii * (16 * ROWSTRIDE_B) + kbB);
        CP_COMMIT();
    };

    load_full(0, 0, 0);
    load_full(1, 128, 128);

    float acc[4][8][4];
#pragma unroll
    for (int a = 0; a < 4; ++a)
#pragma unroll
        for (int b = 0; b < 8; ++b)
#pragma unroll
            for (int c = 0; c < 4; ++c) acc[a][b][c] = 0.f;

    // XOR-folded ldmatrix addressing
    const int lrow = lane & 15;
    const uint32_t lkh = (uint32_t)((lane >> 4) << 4);
    uint32_t preA[4], preB[4];
#pragma unroll
    for (int t = 0; t < 4; ++t) {
        uint32_t rbA = (uint32_t)((wm * 64 + t * 16 + lrow) * 128);
        preA[t] = rbA | (lkh ^ ((rbA >> 3) & 0x70));
        uint32_t rbB = (uint32_t)((wn * 64 + t * 16 + lrow) * 128);
        preB[t] = (rbB | (lkh ^ ((rbB >> 3) & 0x70))) + TILE_B;
    }

    // prefetch byte offsets within a gmem row for chunk i+2
    int kbA = 2 * 128, kbB = 2 * 128;

    for (int i = 0; i < NCH; ++i) {
        if (i == NCH - 1) { CP_WAIT_0(); } else { CP_WAIT_1(); }
        __syncthreads();
        const bool doload = (i + 2 < NCH);
        const uint32_t sld = base + ((i + 2) % STAGES) * STAGE_B;
        const uint32_t sS = base + (i % STAGES) * STAGE_B;

        uint32_t ar[2][4][4], br[2][4][4];
#pragma unroll
        for (int t = 0; t < 4; ++t) {        // ks = 0 fragments
            LDSM_X4(ar[0][t][0], ar[0][t][1], ar[0][t][2], ar[0][t][3], sS + preA[t]);
            LDSM_X4(br[0][t][0], br[0][t][1], br[0][t][2], br[0][t][3], sS + preB[t]);
        }
#pragma unroll
        for (int ks = 0; ks < 4; ++ks) {
            const int cur = ks & 1, nxt = cur ^ 1;
            if (doload) {   // 4 of the 16 next-stage cp.async per ks
                const int i0 = 2 * ks, i1 = 2 * ks + 1;
                CP_ASYNC16(sld + offs[i0], gAt + (size_t)i0 * (16 * ROWSTRIDE_B) + kbA);
                CP_ASYNC16(sld + offs[i1], gAt + (size_t)i1 * (16 * ROWSTRIDE_B) + kbA);
                CP_ASYNC16(sld + TILE_B + offs[i0], gBt + (size_t)i0 * (16 * ROWSTRIDE_B) + kbB);
                CP_ASYNC16(sld + TILE_B + offs[i1], gBt + (size_t)i1 * (16 * ROWSTRIDE_B) + kbB);
            }
            if (ks < 3) {   // prefetch fragments for ks+1
                const uint32_t kx = (uint32_t)((ks + 1) << 5);
#pragma unroll
                for (int t = 0; t < 4; ++t) {
                    LDSM_X4(ar[nxt][t][0], ar[nxt][t][1], ar[nxt][t][2], ar[nxt][t][3],
                            (sS + preA[t]) ^ kx);
                    LDSM_X4(br[nxt][t][0], br[nxt][t][1], br[nxt][t][2], br[nxt][t][3],
                            (sS + preB[t]) ^ kx);
                }
            }
#pragma unroll
            for (int tm = 0; tm < 4; ++tm)
#pragma unroll
                for (int tn = 0; tn < 8; ++tn)
                    mma_bf16(acc[tm][tn], ar[cur][tm],
                             br[cur][tn >> 1][tn & 1], br[cur][tn >> 1][2 + (tn & 1)]);
        }
        if (doload) CP_COMMIT();
        // advance prefetch offsets for chunk i+3 (wrap at segment ends)
        kbA += 128; kbB += 128;
        if (i + 3 == 128) kbA = 0;          // A: [xh|xl|xh] wraps at c=128
        if (i + 3 == 64)  kbB = 0;          // B: [wh|wh|wl] wraps at c=64
        else if (i + 3 == 128) kbB = 128 * 64;   // B: c>=128 -> wl segment
    }

    // ------------- fused epilogue: out = acc + bias + 2 * h @ B[slot] -------
    __syncthreads();                       // stage smem now reusable
    float* sH    = (float*)p_base;         // 128 x 16 (8KB)
    float* sBm   = sH + 2048;              // 16 x 128 (8KB)
    float* sbias = sBm + 2048;             // 128 (512B)
    const int slot = map[m0 >> 10];
    {
        const float4* hs = (const float4*)(h + (size_t)m0 * 16);
#pragma unroll
        for (int q = tid; q < 512; q += 128) ((float4*)sH)[q] = hs[q];
        const float* Bbase = Bs + (size_t)slot * RR * OUTF + n0;
#pragma unroll
        for (int q = tid; q < 512; q += 128) {
            int r = q >> 5, c4 = q & 31;
            ((float4*)sBm)[q] = *(const float4*)(Bbase + (size_t)r * OUTF + c4 * 4);
        }
        if (tid < 32) ((float4*)sbias)[tid] = ((const float4*)(bias + n0))[tid];
    }
    __syncthreads();

    const int erow = lane >> 2, ecol = (lane & 3) * 2;
#pragma unroll
    for (int tm = 0; tm < 4; ++tm) {
        const int r0 = wm * 64 + tm * 16 + erow;
#pragma unroll
        for (int tn = 0; tn < 8; ++tn) {
            const int nl = wn * 64 + tn * 8 + ecol;
            float d00 = 0.f, d01 = 0.f, d10 = 0.f, d11 = 0.f;
#pragma unroll
            for (int r = 0; r < 16; ++r) {
                float hv0 = sH[r0 * 16 + r], hv1 = sH[(r0 + 8) * 16 + r];
                float B0 = sBm[r * 128 + nl], B1 = sBm[r * 128 + nl + 1];
                d00 += hv0 * B0; d01 += hv0 * B1;
                d10 += hv1 * B0; d11 += hv1 * B1;
            }
            const float b0 = sbias[nl], b1 = sbias[nl + 1];
            float* p = out + (size_t)(m0 + r0) * OUTF + n0 + nl;
            *(float2*)p = make_float2(acc[tm][tn][0] + b0 + SCALING_F * d00,
                                      acc[tm][tn][1] + b1 + SCALING_F * d01);
            *(float2*)(p + (size_t)8 * OUTF) =
                make_float2(acc[tm][tn][2] + b0 + SCALING_F * d10,
                            acc[tm][tn][3] + b1 + SCALING_F * d11);
        }
    }
}

// ---------------------------------------------------------------------------
extern "C" void kernel_launch(void* const* d_in, const int* in_sizes, int n_in,
                              void* d_out, int out_size) {
    const float* x    = (const float*)d_in[0];
    const int*   map  = (const int*)d_in[1];
    const float* W    = (const float*)d_in[2];
    const float* bias = (const float*)d_in[3];
    const float* As   = (const float*)d_in[4];
    const float* Bs   = (const float*)d_in[5];
    float* out = (float*)d_out;

    __nv_bfloat16 *xa, *wb;
    float* hbuf;
    cudaGetSymbolAddress((void**)&xa, g_xa);
    cudaGetSymbolAddress((void**)&wb, g_wb);
    cudaGetSymbolAddress((void**)&hbuf, g_h);

    cudaFuncSetAttribute(k_gemm, cudaFuncAttributeMaxDynamicSharedMemorySize,
                         (int)GEMM_SMEM);

    k_split<<<2048, 256>>>(x, xa, M_TOT * (INF / 4));
    k_split<<<1024, 256>>>(W, wb, OUTF * (INF / 4));
    k_lorah<<<M_TOT / 64, 256>>>(x, As, map, hbuf);
    k_gemm<<<dim3(OUTF / 128, M_TOT / 128), 128, GEMM_SMEM>>>(
        xa, wb, bias, Bs, map, hbuf, out);
}

// round 6
// speedup vs baseline: 1.0759x; 1.0398x over previous
#include <cuda_runtime.h>
#include <cuda_bf16.h>
#include <cstdint>

// ---------------------------------------------------------------------------
// DynamicLoRALinear on GB300 (sm_103 baseline PTX; tcgen05 not available)
//   out = x @ W^T + b + SCALING * ((x @ A[slot]) @ B[slot])
//
//   1) 3xBF16 split, K folded: logical K' = 12288, term order
//      [xh*wh | xl*wh | xh*wl], stored dedup as x'=[xh|xl], w'=[wh|wl].
//   2) mma.sync.m16n8k16 GEMM: CTA 128x128, 4 warps (64x64 warp tile),
//      3-stage cp.async pipeline interleaved into the MMA stream,
//      SW128 swizzle + ldmatrix. Fused epilogue adds bias + 2*h@B[slot].
//      (Best-measured R3 configuration, unchanged.)
//   3) k_lorah rewritten register-blocked: 4 FMA per LDS.128, no reduction.
// ---------------------------------------------------------------------------

#define DINLINE __device__ __forceinline__

static constexpr int BB    = 8;
static constexpr int TT    = 1024;
static constexpr int INF   = 4096;
static constexpr int OUTF  = 4096;
static constexpr int RR    = 16;
static constexpr int M_TOT = BB * TT;          // 8192
static constexpr int KW    = 2 * INF;          // physical row width 8192
static constexpr int NCH   = 192;              // logical K' chunks of 64
static constexpr float SCALING_F = 2.0f;       // ALPHA/R

// ------------------------- scratch (device globals) ------------------------
__device__ __align__(128) __nv_bfloat16 g_xa[(size_t)M_TOT * KW]; // [xh|xl]
__device__ __align__(128) __nv_bfloat16 g_wb[(size_t)OUTF  * KW]; // [wh|wl]
__device__ __align__(128) float         g_h[M_TOT * RR];

// ------------------------------ PTX helpers --------------------------------
DINLINE uint32_t smem_u32(const void* p) {
    uint32_t a;
    asm("{ .reg .u64 t; cvta.to.shared.u64 t, %1; cvt.u32.u64 %0, t; }"
        : "=r"(a) : "l"(p));
    return a;
}

#define SW128(off) ((off) ^ (((off) >> 3) & 0x70))

#define CP_ASYNC16(dst, src) \
    asm volatile("cp.async.cg.shared.global [%0], [%1], 16;" :: "r"(dst), "l"(src) : "memory")
#define CP_COMMIT() asm volatile("cp.async.commit_group;" ::: "memory")
#define CP_WAIT_1() asm volatile("cp.async.wait_group 1;" ::: "memory")
#define CP_WAIT_0() asm volatile("cp.async.wait_group 0;" ::: "memory")

#define LDSM_X4(r0, r1, r2, r3, a) \
    asm volatile("ldmatrix.sync.aligned.m8n8.x4.shared.b16 {%0,%1,%2,%3}, [%4];" \
                 : "=r"(r0), "=r"(r1), "=r"(r2), "=r"(r3) : "r"(a))

DINLINE void mma_bf16(float* d, const uint32_t* a, uint32_t b0, uint32_t b1) {
    asm volatile(
        "mma.sync.aligned.m16n8k16.row.col.f32.bf16.bf16.f32 "
        "{%0,%1,%2,%3}, {%4,%5,%6,%7}, {%8,%9}, {%0,%1,%2,%3};"
        : "+f"(d[0]), "+f"(d[1]), "+f"(d[2]), "+f"(d[3])
        : "r"(a[0]), "r"(a[1]), "r"(a[2]), "r"(a[3]), "r"(b0), "r"(b1));
}

// ---------------------------------------------------------------------------
// K1: split fp32 rows of INF -> bf16 rows of KW: hi at [k], lo at [INF+k]
// ---------------------------------------------------------------------------
__global__ void __launch_bounds__(256)
k_split(const float* __restrict__ in, __nv_bfloat16* __restrict__ out, int total4) {
    const int stride = gridDim.x * blockDim.x;
    for (int i = blockIdx.x * blockDim.x + threadIdx.x; i < total4; i += stride) {
        const int row = i >> 10, c4 = i & 1023;
        float4 v = ((const float4*)in)[i];
        __nv_bfloat16 h0 = __float2bfloat16(v.x);
        __nv_bfloat16 h1 = __float2bfloat16(v.y);
        __nv_bfloat16 h2 = __float2bfloat16(v.z);
        __nv_bfloat16 h3 = __float2bfloat16(v.w);
        __nv_bfloat162 hA = {h0, h1}, hB = {h2, h3};
        __nv_bfloat162 lA = {__float2bfloat16(v.x - __bfloat162float(h0)),
                             __float2bfloat16(v.y - __bfloat162float(h1))};
        __nv_bfloat162 lB = {__float2bfloat16(v.z - __bfloat162float(h2)),
                             __float2bfloat16(v.w - __bfloat162float(h3))};
        const size_t rb = (size_t)row * KW;
        __nv_bfloat162* p;
        p = (__nv_bfloat162*)(out + rb + c4 * 4);        p[0] = hA; p[1] = hB;
        p = (__nv_bfloat162*)(out + rb + INF + c4 * 4);  p[0] = lA; p[1] = lB;
    }
}

// ---------------------------------------------------------------------------
// K2: lora_h[m][r] = sum_k x[m][k] * A[slot(m)][k][r]    (fp32)
// Register-blocked: block = 64 tokens x 16 r, 256 threads.
// thread = (token, r-quartet): acc[4] in regs, per k: 1 LDS.128 + 4 FFMA.
// A staged per 256-k chunk in smem [256][16] (16KB). No reduction step.
// ---------------------------------------------------------------------------
__global__ void __launch_bounds__(256)
k_lorah(const float* __restrict__ x, const float* __restrict__ As,
        const int* __restrict__ map, float* __restrict__ h) {
    __shared__ float sA[256 * 16];          // 16KB: A chunk [k][r]
    const int tid = threadIdx.x;
    const int m0  = blockIdx.x * 64;
    const int slot = map[m0 / TT];
    const float* Abase = As + (size_t)slot * INF * RR;
    const int tok = tid >> 2;               // 0..63
    const int rq  = tid & 3;                // r-quartet 0..3
    const float* xrow = x + (size_t)(m0 + tok) * INF;

    float acc0 = 0.f, acc1 = 0.f, acc2 = 0.f, acc3 = 0.f;

    for (int c = 0; c < 16; ++c) {          // 16 chunks of 256 k
        __syncthreads();
        // stage A[c*256 .. c*256+255][0..15]: 1024 float4, 4 per thread
        const float4* src = (const float4*)(Abase + (size_t)c * 256 * 16);
#pragma unroll
        for (int ii = 0; ii < 4; ++ii)
            ((float4*)sA)[tid + ii * 256] = src[tid + ii * 256];
        __syncthreads();

        const float* xc = xrow + c * 256;
#pragma unroll 4
        for (int j = 0; j < 64; ++j) {      // 4 k per iter
            float4 xv = *(const float4*)(xc + j * 4);
            const float* a0 = sA + (j * 4 + 0) * 16 + rq * 4;
            float4 A0 = *(const float4*)a0;
            float4 A1 = *(const float4*)(a0 + 16);
            float4 A2 = *(const float4*)(a0 + 32);
            float4 A3 = *(const float4*)(a0 + 48);
            acc0 += xv.x * A0.x + xv.y * A1.x + xv.z * A2.x + xv.w * A3.x;
            acc1 += xv.x * A0.y + xv.y * A1.y + xv.z * A2.y + xv.w * A3.y;
            acc2 += xv.x * A0.z + xv.y * A1.z + xv.z * A2.z + xv.w * A3.z;
            acc3 += xv.x * A0.w + xv.y * A1.w + xv.z * A2.w + xv.w * A3.w;
        }
    }

    *(float4*)(h + (size_t)(m0 + tok) * 16 + rq * 4) =
        make_float4(acc0, acc1, acc2, acc3);
}

// ---------------------------------------------------------------------------
// K3: GEMM + fused epilogue. CTA 128x128, 128 threads, warp grid 2x2 (64x64).
// (Best-measured R3 configuration, unchanged.)
// ---------------------------------------------------------------------------
static constexpr int TILE_B  = 128 * 128;      // 16KB
static constexpr int STAGE_B = 2 * TILE_B;     // 32KB
static constexpr int STAGES  = 3;
static constexpr uint32_t GEMM_SMEM = STAGES * STAGE_B + 1024;
static constexpr int ROWSTRIDE_B = KW * 2;     // 16384 bytes per gmem row

DINLINE int kmapA(int c) { return c < 128 ? c : c - 128; }  // [xh|xl|xh]
DINLINE int kmapB(int c) { return c < 64  ? c : c - 64;  }  // [wh|wh|wl]

__global__ void __launch_bounds__(128, 2)
k_gemm(const __nv_bfloat16* __restrict__ Abuf,
       const __nv_bfloat16* __restrict__ Bbuf,
       const float* __restrict__ bias,
       const float* __restrict__ Bs,
       const int* __restrict__ map,
       const float* __restrict__ h,
       float* __restrict__ out) {
    extern __shared__ char smraw[];
    const uint32_t raw  = smem_u32(smraw);
    const uint32_t base = (raw + 1023u) & ~1023u;
    char* p_base = smraw + (base - raw);
    const int tid = threadIdx.x, wid = tid >> 5, lane = tid & 31;
    const int wm = wid >> 1, wn = wid & 1;
    const int m0 = blockIdx.y * 128, n0 = blockIdx.x * 128;

    // per-thread load geometry (constant): 8 rows each for A and B tiles
    const char* gAt = (const char*)(Abuf + (size_t)m0 * KW)
                      + (size_t)(tid >> 3) * ROWSTRIDE_B + (tid & 7) * 16;
    const char* gBt = (const char*)(Bbuf + (size_t)n0 * KW)
                      + (size_t)(tid >> 3) * ROWSTRIDE_B + (tid & 7) * 16;
    uint32_t offs[8];
#pragma unroll
    for (int ii = 0; ii < 8; ++ii)
        offs[ii] = SW128((uint32_t)((((tid >> 3) + 16 * ii) * 128) + (tid & 7) * 16));

    auto load_full = [&](int s, int c) {
        const uint32_t sb = base + s * STAGE_B;
        const int kbA = kmapA(c) * 128, kbB = kmapB(c) * 128;
#pragma unroll
        for (int ii = 0; ii < 8; ++ii)
            CP_ASYNC16(sb + offs[ii], gAt + (size_t)ii * (16 * ROWSTRIDE_B) + kbA);
#pragma unroll
        for (int ii = 0; ii < 8; ++ii)
            CP_ASYNC16(sb + TILE_B + offs[ii], gBt + (size_t)ii * (16 * ROWSTRIDE_B) + kbB);
        CP_COMMIT();
    };

    load_full(0, 0);
    load_full(1, 1);

    float acc[4][8][4];
#pragma unroll
    for (int a = 0; a < 4; ++a)
#pragma unroll
        for (int b = 0; b < 8; ++b)
#pragma unroll
            for (int c = 0; c < 4; ++c) acc[a][b][c] = 0.f;

    const int lrow = lane & 15;
    const uint32_t lkh = (uint32_t)((lane >> 4) << 4);

    for (int i = 0; i < NCH; ++i) {
        if (i == NCH - 1) { CP_WAIT_0(); } else { CP_WAIT_1(); }
        __syncthreads();
        const bool doload = (i + 2 < NCH);
        const uint32_t sld = base + ((i + 2) % STAGES) * STAGE_B;
        const int kbA = kmapA(i + 2) * 128, kbB = kmapB(i + 2) * 128;
        const uint32_t sA = base + (i % STAGES) * STAGE_B;
        const uint32_t sB = sA + TILE_B;
#pragma unroll
        for (int ks = 0; ks < 4; ++ks) {
            if (doload) {   // interleave 4 of the 16 next-stage loads per ks
                const int i0 = 2 * ks, i1 = 2 * ks + 1;
                CP_ASYNC16(sld + offs[i0],
                           gAt + (size_t)i0 * (16 * ROWSTRIDE_B) + kbA);
                CP_ASYNC16(sld + offs[i1],
                           gAt + (size_t)i1 * (16 * ROWSTRIDE_B) + kbA);
                CP_ASYNC16(sld + TILE_B + offs[i0],
                           gBt + (size_t)i0 * (16 * ROWSTRIDE_B) + kbB);
                CP_ASYNC16(sld + TILE_B + offs[i1],
                           gBt + (size_t)i1 * (16 * ROWSTRIDE_B) + kbB);
            }
            const uint32_t kc = (uint32_t)(ks * 32) + lkh;
            uint32_t ar[4][4], br[4][4];
#pragma unroll
            for (int t = 0; t < 4; ++t) {
                uint32_t a = sA + SW128((uint32_t)((wm * 64 + t * 16 + lrow) * 128) + kc);
                LDSM_X4(ar[t][0], ar[t][1], ar[t][2], ar[t][3], a);
            }
#pragma unroll
            for (int t = 0; t < 4; ++t) {
                uint32_t a = sB + SW128((uint32_t)((wn * 64 + t * 16 + lrow) * 128) + kc);
                LDSM_X4(br[t][0], br[t][1], br[t][2], br[t][3], a);
            }
#pragma unroll
            for (int tm = 0; tm < 4; ++tm)
#pragma unroll
                for (int tn = 0; tn < 8; ++tn)
                    mma_bf16(acc[tm][tn], ar[tm],
                             br[tn >> 1][tn & 1], br[tn >> 1][2 + (tn & 1)]);
        }
        if (doload) CP_COMMIT();
    }

    // ---------------- fused epilogue: out = acc + bias + 2 * h @ B[slot] ----
    float* sH    = (float*)p_base;        // 128 x 16  (8KB)
    float* sBm   = sH + 2048;             // 16 x 128  (8KB)
    float* sbias = sBm + 2048;            // 128       (512B)
    const int slot = map[m0 >> 10];
    {
        const float4* hs = (const float4*)(h + (size_t)m0 * 16);
#pragma unroll
        for (int q = tid; q < 512; q += 128) ((float4*)sH)[q] = hs[q];
        const float* Bbase = Bs + (size_t)slot * RR * OUTF + n0;
#pragma unroll
        for (int q = tid; q < 512; q += 128) {
            int r = q >> 5, c4 = q & 31;
            ((float4*)sBm)[q] = *(const float4*)(Bbase + (size_t)r * OUTF + c4 * 4);
        }
        if (tid < 32) ((float4*)sbias)[tid] = ((const float4*)(bias + n0))[tid];
    }
    __syncthreads();

    const int erow = lane >> 2, ecol = (lane & 3) * 2;
#pragma unroll
    for (int tm = 0; tm < 4; ++tm) {
        const int r0 = wm * 64 + tm * 16 + erow;     // local rows r0, r0+8
        float h0[16], h1[16];
#pragma unroll
        for (int r = 0; r < 16; ++r) { h0[r] = sH[r0 * 16 + r]; h1[r] = sH[(r0 + 8) * 16 + r]; }
#pragma unroll
        for (int tn = 0; tn < 8; ++tn) {
            const int nl = wn * 64 + tn * 8 + ecol;
            float d00 = 0.f, d01 = 0.f, d10 = 0.f, d11 = 0.f;
#pragma unroll
            for (int r = 0; r < 16; ++r) {
                float B0 = sBm[r * 128 + nl], B1 = sBm[r * 128 + nl + 1];
                d00 += h0[r] * B0; d01 += h0[r] * B1;
                d10 += h1[r] * B0; d11 += h1[r] * B1;
            }
            const float b0 = sbias[nl], b1 = sbias[nl + 1];
            float* p = out + (size_t)(m0 + r0) * OUTF + n0 + nl;
            *(float2*)p = make_float2(acc[tm][tn][0] + b0 + SCALING_F * d00,
                                      acc[tm][tn][1] + b1 + SCALING_F * d01);
            *(float2*)(p + (size_t)8 * OUTF) =
                make_float2(acc[tm][tn][2] + b0 + SCALING_F * d10,
                            acc[tm][tn][3] + b1 + SCALING_F * d11);
        }
    }
}

// ---------------------------------------------------------------------------
extern "C" void kernel_launch(void* const* d_in, const int* in_sizes, int n_in,
                              void* d_out, int out_size) {
    const float* x    = (const float*)d_in[0];
    const int*   map  = (const int*)d_in[1];
    const float* W    = (const float*)d_in[2];
    const float* bias = (const float*)d_in[3];
    const float* As   = (const float*)d_in[4];
    const float* Bs   = (const float*)d_in[5];
    float* out = (float*)d_out;

    __nv_bfloat16 *xa, *wb;
    float* hbuf;
    cudaGetSymbolAddress((void**)&xa, g_xa);
    cudaGetSymbolAddress((void**)&wb, g_wb);
    cudaGetSymbolAddress((void**)&hbuf, g_h);

    cudaFuncSetAttribute(k_gemm, cudaFuncAttributeMaxDynamicSharedMemorySize,
                         (int)GEMM_SMEM);

    k_split<<<2048, 256>>>(x, xa, M_TOT * (INF / 4));
    k_split<<<1024, 256>>>(W, wb, OUTF * (INF / 4));
    k_lorah<<<M_TOT / 64, 256>>>(x, As, map, hbuf);
    k_gemm<<<dim3(OUTF / 128, M_TOT / 128), 128, GEMM_SMEM>>>(
        xa, wb, bias, Bs, map, hbuf, out);
}